// round 14
// baseline (speedup 1.0000x reference)
#include <cuda_runtime.h>
#include <cuda_fp16.h>
#include <cstdint>
#include <math.h>

// Problem constants: b=2, t=8, L=1024, c=256, H=8, D=32
#define M_ROWS 16384
#define CDIM   256
#define NHEAD  8
#define DHEAD  32
#define LSEQ   1024
#define BTH    128

// 1/sqrt(32) folded into Q at projection epilogue
#define QSCALE 0.17677669529663687f

// Scratch (device globals) — all 16-bit tensors are fp16
__device__ __half g_x16[12582912];  // q,k,v inputs
__device__ __half g_w16[262144];    // Wq,Wk,Wv,Wm
__device__ __half g_q16[4194304];   // [bth, l, d]  (pre-scaled)
__device__ __half g_k16[4194304];   // [bth, l, d]
__device__ __half g_v16[4194304];   // [bth, l, d]
__device__ __half g_att16[4194304]; // [bt, l, c]

// ---------------------------------------------------------------------------
__device__ __forceinline__ uint32_t smem_u32(const void* p) {
    uint32_t a;
    asm("{ .reg .u64 t; cvta.to.shared.u64 t, %1; cvt.u32.u64 %0, t; }" : "=r"(a) : "l"(p));
    return a;
}

#define LDSM_X4(r0, r1, r2, r3, addr) \
    asm volatile("ldmatrix.sync.aligned.m8n8.x4.shared.b16 {%0,%1,%2,%3}, [%4];" \
                 : "=r"(r0), "=r"(r1), "=r"(r2), "=r"(r3) : "r"(addr))
#define LDSM_X4T(r0, r1, r2, r3, addr) \
    asm volatile("ldmatrix.sync.aligned.m8n8.x4.trans.shared.b16 {%0,%1,%2,%3}, [%4];" \
                 : "=r"(r0), "=r"(r1), "=r"(r2), "=r"(r3) : "r"(addr))

// f16 operands, f32 accumulator (GEMMs, PV, row sums)
#define MMA_F16F32(c0, c1, c2, c3, a0, a1, a2, a3, b0, b1) \
    asm volatile("mma.sync.aligned.m16n8k16.row.col.f32.f16.f16.f32 " \
                 "{%0,%1,%2,%3}, {%4,%5,%6,%7}, {%8,%9}, {%0,%1,%2,%3};" \
                 : "+f"(c0), "+f"(c1), "+f"(c2), "+f"(c3) \
                 : "r"(a0), "r"(a1), "r"(a2), "r"(a3), "r"(b0), "r"(b1))

// f16 operands, f16 accumulator (QK^T): D/C are 2 packed f16x2 regs
#define MMA_F16ACC(d0, d1, a0, a1, a2, a3, b0, b1) \
    asm volatile("mma.sync.aligned.m16n8k16.row.col.f16.f16.f16.f16 " \
                 "{%0,%1}, {%2,%3,%4,%5}, {%6,%7}, {%0,%1};" \
                 : "+r"(d0), "+r"(d1) \
                 : "r"(a0), "r"(a1), "r"(a2), "r"(a3), "r"(b0), "r"(b1))

#define CVT_F16X2(r, hi, lo) \
    asm("cvt.rn.f16x2.f32 %0, %1, %2;" : "=r"(r) : "f"(hi), "f"(lo))

#define HFMA2_F16(d, a, b, cc) \
    asm("fma.rn.f16x2 %0, %1, %2, %3;" : "=r"(d) : "r"(a), "r"(b), "r"(cc))

#define CP16(dst, src) \
    asm volatile("cp.async.cg.shared.global [%0], [%1], 16;" :: "r"(dst), "l"(src))
#define CP_COMMIT() asm volatile("cp.async.commit_group;")
#define CP_WAIT(n)  asm volatile("cp.async.wait_group %0;" :: "n"(n))

// f16x2 constants
#define ONES_F16X2  0x3C003C00u   // (1.0, 1.0)
#define HALF_F16X2  0x38003800u   // (0.5, 0.5)

// exp(x) for |x| <= 0.18: degree-2 Taylor in packed f16x2
__device__ __forceinline__ uint32_t exp_f16x2(uint32_t x) {
    uint32_t t;
    HFMA2_F16(t, x, HALF_F16X2, ONES_F16X2);
    HFMA2_F16(t, x, t, ONES_F16X2);
    return t;
}

// ---------------------------------------------------------------------------
// Kernel 0: fp32 -> fp16 conversion of q,k,v and the 4 weight matrices.
// ---------------------------------------------------------------------------
#define XQ 1048576
#define WQ 16384
__global__ __launch_bounds__(256) void convert_kernel(
    const float* __restrict__ q, const float* __restrict__ k, const float* __restrict__ v,
    const float* __restrict__ Wq, const float* __restrict__ Wk,
    const float* __restrict__ Wv, const float* __restrict__ Wm)
{
    int idx = blockIdx.x * 256 + threadIdx.x;
    const float* src;
    uint2* dst;
    int local;
    if (idx < 3 * XQ) {
        int sel = idx / XQ;
        local = idx - sel * XQ;
        src = (sel == 0) ? q : (sel == 1) ? k : v;
        dst = (uint2*)g_x16 + idx;
    } else {
        int wi = idx - 3 * XQ;
        int sel = wi / WQ;
        local = wi - sel * WQ;
        src = (sel == 0) ? Wq : (sel == 1) ? Wk : (sel == 2) ? Wv : Wm;
        dst = (uint2*)g_w16 + wi;
    }
    float4 vv = ((const float4*)src)[local];
    uint32_t lo, hi;
    CVT_F16X2(lo, vv.y, vv.x);
    CVT_F16X2(hi, vv.w, vv.z);
    *dst = make_uint2(lo, hi);
}

// ---------------------------------------------------------------------------
// Kernel 1: merged q/k/v fp16 GEMM projection.
// 3-stage cp.async pipeline (prefetch distance 2), ONE barrier per chunk.
// ---------------------------------------------------------------------------
__global__ __launch_bounds__(256, 2) void qkv_proj_kernel(
    const float* __restrict__ bq, const float* __restrict__ bk,
    const float* __restrict__ bv)
{
    __shared__ __half Xs[3][128][40];
    __shared__ __half Ws[3][128][40];

    const int sel = blockIdx.z;
    const __half* X = g_x16 + (size_t)sel * 4194304;
    const __half* W = g_w16 + sel * 65536;
    const float* bias = (sel == 0) ? bq : (sel == 1) ? bk : bv;
    const float extra = (sel == 0) ? QSCALE : 1.0f;
    __half* Out = (sel == 0) ? g_q16 : (sel == 1) ? g_k16 : g_v16;

    const int tid = threadIdx.x;
    const int w = tid >> 5, lane = tid & 31;
    const int wm = w >> 1, wn = w & 1;
    const int groupID = lane >> 2, tid4 = lane & 3;
    const int rowBase = blockIdx.x * 128;
    const int colBase = blockIdx.y * 128;

    const int lr0 = tid >> 2, lp0 = tid & 3;
    const int lr1 = lr0 + 64;

    float c[2][8][4];
#pragma unroll
    for (int mt = 0; mt < 2; ++mt)
#pragma unroll
        for (int nt = 0; nt < 8; ++nt)
#pragma unroll
            for (int i = 0; i < 4; ++i) c[mt][nt][i] = 0.f;

#pragma unroll
    for (int pc = 0; pc < 2; ++pc) {
        int ko = pc * 32;
        CP16(smem_u32(&Xs[pc][lr0][lp0 * 8]), X + (size_t)(rowBase + lr0) * CDIM + ko + lp0 * 8);
        CP16(smem_u32(&Xs[pc][lr1][lp0 * 8]), X + (size_t)(rowBase + lr1) * CDIM + ko + lp0 * 8);
        CP16(smem_u32(&Ws[pc][lr0][lp0 * 8]), W + (size_t)(colBase + lr0) * CDIM + ko + lp0 * 8);
        CP16(smem_u32(&Ws[pc][lr1][lp0 * 8]), W + (size_t)(colBase + lr1) * CDIM + ko + lp0 * 8);
        CP_COMMIT();
    }

#pragma unroll
    for (int kt = 0; kt < 8; ++kt) {
        const int cb = kt % 3;
        if (kt < 7) { CP_WAIT(1); } else { CP_WAIT(0); }
        __syncthreads();
        if (kt < 6) {
            const int nb = (kt + 2) % 3;
            int ko = (kt + 2) * 32;
            CP16(smem_u32(&Xs[nb][lr0][lp0 * 8]), X + (size_t)(rowBase + lr0) * CDIM + ko + lp0 * 8);
            CP16(smem_u32(&Xs[nb][lr1][lp0 * 8]), X + (size_t)(rowBase + lr1) * CDIM + ko + lp0 * 8);
            CP16(smem_u32(&Ws[nb][lr0][lp0 * 8]), W + (size_t)(colBase + lr0) * CDIM + ko + lp0 * 8);
            CP16(smem_u32(&Ws[nb][lr1][lp0 * 8]), W + (size_t)(colBase + lr1) * CDIM + ko + lp0 * 8);
            CP_COMMIT();
        }

        uint32_t a[2][2][4];
#pragma unroll
        for (int mt = 0; mt < 2; ++mt)
#pragma unroll
            for (int ks = 0; ks < 2; ++ks) {
                uint32_t addr = smem_u32(
                    &Xs[cb][wm * 32 + mt * 16 + (lane & 7) + ((lane & 8) ? 8 : 0)]
                       [ks * 16 + ((lane & 16) ? 8 : 0)]);
                LDSM_X4(a[mt][ks][0], a[mt][ks][1], a[mt][ks][2], a[mt][ks][3], addr);
            }
#pragma unroll
        for (int nt = 0; nt < 8; ++nt) {
            uint32_t b[4];
            uint32_t addr = smem_u32(&Ws[cb][wn * 64 + nt * 8 + (lane & 7)][(lane >> 3) * 8]);
            LDSM_X4(b[0], b[1], b[2], b[3], addr);
#pragma unroll
            for (int mt = 0; mt < 2; ++mt) {
                MMA_F16F32(c[mt][nt][0], c[mt][nt][1], c[mt][nt][2], c[mt][nt][3],
                           a[mt][0][0], a[mt][0][1], a[mt][0][2], a[mt][0][3], b[0], b[1]);
                MMA_F16F32(c[mt][nt][0], c[mt][nt][1], c[mt][nt][2], c[mt][nt][3],
                           a[mt][1][0], a[mt][1][1], a[mt][1][2], a[mt][1][3], b[2], b[3]);
            }
        }
    }

    float2 bj[8];
#pragma unroll
    for (int nt = 0; nt < 8; ++nt)
        bj[nt] = *(const float2*)(bias + colBase + wn * 64 + nt * 8 + tid4 * 2);
#pragma unroll
    for (int mt = 0; mt < 2; ++mt)
#pragma unroll
        for (int nt = 0; nt < 8; ++nt) {
            c[mt][nt][0] += bj[nt].x; c[mt][nt][1] += bj[nt].y;
            c[mt][nt][2] += bj[nt].x; c[mt][nt][3] += bj[nt].y;
        }

#pragma unroll
    for (int mt = 0; mt < 2; ++mt) {
        float ss[2][2];
        ss[0][0] = ss[0][1] = ss[1][0] = ss[1][1] = 0.f;
#pragma unroll
        for (int nt = 0; nt < 8; ++nt) {
            int hd = nt >> 2;
            ss[0][hd] += c[mt][nt][0] * c[mt][nt][0] + c[mt][nt][1] * c[mt][nt][1];
            ss[1][hd] += c[mt][nt][2] * c[mt][nt][2] + c[mt][nt][3] * c[mt][nt][3];
        }
        float scl[2][2];
#pragma unroll
        for (int rh = 0; rh < 2; ++rh)
#pragma unroll
            for (int hd = 0; hd < 2; ++hd) {
                float s = ss[rh][hd];
                s += __shfl_xor_sync(0xffffffffu, s, 1);
                s += __shfl_xor_sync(0xffffffffu, s, 2);
                scl[rh][hd] = extra / fmaxf(sqrtf(s), 1e-12f);
            }
#pragma unroll
        for (int rh = 0; rh < 2; ++rh) {
            int grow = rowBase + wm * 32 + mt * 16 + groupID + rh * 8;
            int bt = grow >> 10, l = grow & 1023;
#pragma unroll
            for (int nt = 0; nt < 8; ++nt) {
                int j = colBase + wn * 64 + nt * 8 + tid4 * 2;
                int h = j >> 5, dd = j & 31;
                float sc = scl[rh][nt >> 2];
                uint32_t pk;
                CVT_F16X2(pk, c[mt][nt][rh * 2 + 1] * sc, c[mt][nt][rh * 2 + 0] * sc);
                *(uint32_t*)(Out + (((size_t)bt * NHEAD + h) * LSEQ + l) * DHEAD + dd) = pk;
            }
        }
    }
}

// ---------------------------------------------------------------------------
// Kernel 2: fp16 flash attention, m32 rows/warp, 128 threads.
// Partitioned padding-free smem layout [part][row][8] -> 8KB/tile, 32KB/CTA
// total -> 4 CTAs/SM (vs 2 with padded rows). cp.async double-buffered,
// ONE barrier per tile. QK^T with f16 accumulator; exp in-place; row sums
// on tensor pipe; no online max (|s| <= 0.177).
// ---------------------------------------------------------------------------
__global__ __launch_bounds__(128, 4) void attn_mma_kernel()
{
    // [buf][part = col/8][row][8 halfs]; cell (row,part) is 16B aligned.
    __shared__ __half sK[2][4][128][8];
    __shared__ __half sV[2][4][128][8];

    const int tid = threadIdx.x;
    const int w = tid >> 5, lane = tid & 31;
    const int groupID = lane >> 2, tid4 = lane & 3;
    const int bth = blockIdx.y, qt = blockIdx.x;

    const char* Qg = (const char*)(g_q16 + ((size_t)bth * LSEQ + qt * 128) * DHEAD);
    const char* Kg = (const char*)(g_k16 + (size_t)bth * LSEQ * DHEAD);
    const char* Vg = (const char*)(g_v16 + (size_t)bth * LSEQ * DHEAD);

    // Stage Q through sK[0] (partitioned layout; float4 stores are 16B aligned)
#pragma unroll
    for (int i = 0; i < 4; ++i) {
        int f = tid + i * 128;
        int row = f >> 2, part = f & 3;
        *(float4*)(&sK[0][part][row][0]) = *(const float4*)(Qg + row * 64 + part * 16);
    }
    __syncthreads();

    uint32_t qa[2][2][4];
#pragma unroll
    for (int mt = 0; mt < 2; ++mt)
#pragma unroll
        for (int kc = 0; kc < 2; ++kc) {
            int row = w * 32 + mt * 16 + (lane & 7) + ((lane & 8) ? 8 : 0);
            int part = kc * 2 + ((lane & 16) ? 1 : 0);
            uint32_t addr = smem_u32(&sK[0][part][row][0]);
            LDSM_X4(qa[mt][kc][0], qa[mt][kc][1], qa[mt][kc][2], qa[mt][kc][3], addr);
        }
    __syncthreads();

    // prologue: tile 0 -> buf 0
#pragma unroll
    for (int i = 0; i < 4; ++i) {
        int f = tid + i * 128;
        int row = f >> 2, part = f & 3;
        CP16(smem_u32(&sK[0][part][row][0]), Kg + (size_t)row * 64 + part * 16);
        CP16(smem_u32(&sV[0][part][row][0]), Vg + (size_t)row * 64 + part * 16);
    }
    CP_COMMIT();

    float o[2][4][4];
    float su[2][4];
#pragma unroll
    for (int mt = 0; mt < 2; ++mt) {
#pragma unroll
        for (int dn = 0; dn < 4; ++dn)
#pragma unroll
            for (int i = 0; i < 4; ++i) o[mt][dn][i] = 0.f;
#pragma unroll
        for (int i = 0; i < 4; ++i) su[mt][i] = 0.f;
    }

    for (int kt = 0; kt < 8; ++kt) {
        const int cb = kt & 1;
        CP_WAIT(0);
        __syncthreads();
        if (kt < 7) {
            const int nb = (kt + 1) & 1;
            const char* Kt = Kg + (size_t)(kt + 1) * 128 * 64;
            const char* Vt = Vg + (size_t)(kt + 1) * 128 * 64;
#pragma unroll
            for (int i = 0; i < 4; ++i) {
                int f = tid + i * 128;
                int row = f >> 2, part = f & 3;
                CP16(smem_u32(&sK[nb][part][row][0]), Kt + (size_t)row * 64 + part * 16);
                CP16(smem_u32(&sV[nb][part][row][0]), Vt + (size_t)row * 64 + part * 16);
            }
            CP_COMMIT();
        }

#pragma unroll
        for (int half = 0; half < 2; ++half) {
#pragma unroll
            for (int kc = 0; kc < 4; ++kc) {
                uint32_t pa[2][4];
#pragma unroll
                for (int sub = 0; sub < 2; ++sub) {
                    int nbk = half * 64 + (kc * 2 + sub) * 8;
                    uint32_t kb[4];
                    // B-fragment: row = nbk + (lane&7), part = lane>>3
                    uint32_t addr = smem_u32(&sK[cb][lane >> 3][nbk + (lane & 7)][0]);
                    LDSM_X4(kb[0], kb[1], kb[2], kb[3], addr);
#pragma unroll
                    for (int mt = 0; mt < 2; ++mt) {
                        uint32_t d0 = 0u, d1 = 0u;
                        MMA_F16ACC(d0, d1,
                                   qa[mt][0][0], qa[mt][0][1], qa[mt][0][2], qa[mt][0][3],
                                   kb[0], kb[1]);
                        MMA_F16ACC(d0, d1,
                                   qa[mt][1][0], qa[mt][1][1], qa[mt][1][2], qa[mt][1][3],
                                   kb[2], kb[3]);
                        pa[mt][sub * 2 + 0] = exp_f16x2(d0);
                        pa[mt][sub * 2 + 1] = exp_f16x2(d1);
                    }
                }
#pragma unroll
                for (int dp = 0; dp < 2; ++dp) {
                    uint32_t vb[4];
                    // trans fragment: row = half*64+kc*16+(lane&15),
                    // part = dp*2 + ((lane&16)?1:0)
                    uint32_t addr = smem_u32(
                        &sV[cb][dp * 2 + ((lane & 16) ? 1 : 0)]
                           [half * 64 + kc * 16 + (lane & 15)][0]);
                    LDSM_X4T(vb[0], vb[1], vb[2], vb[3], addr);
#pragma unroll
                    for (int mt = 0; mt < 2; ++mt) {
                        MMA_F16F32(o[mt][2 * dp][0], o[mt][2 * dp][1],
                                   o[mt][2 * dp][2], o[mt][2 * dp][3],
                                   pa[mt][0], pa[mt][1], pa[mt][2], pa[mt][3],
                                   vb[0], vb[1]);
                        MMA_F16F32(o[mt][2 * dp + 1][0], o[mt][2 * dp + 1][1],
                                   o[mt][2 * dp + 1][2], o[mt][2 * dp + 1][3],
                                   pa[mt][0], pa[mt][1], pa[mt][2], pa[mt][3],
                                   vb[2], vb[3]);
                    }
                }
#pragma unroll
                for (int mt = 0; mt < 2; ++mt)
                    MMA_F16F32(su[mt][0], su[mt][1], su[mt][2], su[mt][3],
                               pa[mt][0], pa[mt][1], pa[mt][2], pa[mt][3],
                               ONES_F16X2, ONES_F16X2);
            }
        }
    }

    const int bt = bth >> 3, h = bth & 7;
#pragma unroll
    for (int mt = 0; mt < 2; ++mt) {
        const float inv0 = 1.f / su[mt][0];
        const float inv1 = 1.f / su[mt][2];
        const int l0 = qt * 128 + w * 32 + mt * 16 + groupID;
#pragma unroll
        for (int dn = 0; dn < 4; ++dn) {
            int col = h * DHEAD + dn * 8 + tid4 * 2;
            uint32_t pk0, pk1;
            CVT_F16X2(pk0, o[mt][dn][1] * inv0, o[mt][dn][0] * inv0);
            CVT_F16X2(pk1, o[mt][dn][3] * inv1, o[mt][dn][2] * inv1);
            *(uint32_t*)(g_att16 + ((size_t)bt * LSEQ + l0) * CDIM + col) = pk0;
            *(uint32_t*)(g_att16 + ((size_t)bt * LSEQ + l0 + 8) * CDIM + col) = pk1;
        }
    }
}

// ---------------------------------------------------------------------------
// Kernel 3: Out = g_att16 @ Wm^T + bm + shortcut (fp32 out).
// 128x128 tiles, 3-stage cp.async pipeline, ONE barrier per chunk.
// ---------------------------------------------------------------------------
__global__ __launch_bounds__(256, 2) void final_f16_kernel(
    const float* __restrict__ bias, const float* __restrict__ shortcut,
    float* __restrict__ Out)
{
    __shared__ __half Xs[3][128][40];
    __shared__ __half Ws[3][128][40];

    const __half* X = g_att16;
    const __half* W = g_w16 + 3 * 65536;

    const int tid = threadIdx.x;
    const int w = tid >> 5, lane = tid & 31;
    const int wm = w >> 1, wn = w & 1;
    const int groupID = lane >> 2, tid4 = lane & 3;
    const int rowBase = blockIdx.x * 128;
    const int colBase = blockIdx.y * 128;

    const int lr0 = tid >> 2, lp0 = tid & 3;
    const int lr1 = lr0 + 64;

    float c[2][8][4];
#pragma unroll
    for (int mt = 0; mt < 2; ++mt)
#pragma unroll
        for (int nt = 0; nt < 8; ++nt)
#pragma unroll
            for (int i = 0; i < 4; ++i) c[mt][nt][i] = 0.f;

#pragma unroll
    for (int pc = 0; pc < 2; ++pc) {
        int ko = pc * 32;
        CP16(smem_u32(&Xs[pc][lr0][lp0 * 8]), X + (size_t)(rowBase + lr0) * CDIM + ko + lp0 * 8);
        CP16(smem_u32(&Xs[pc][lr1][lp0 * 8]), X + (size_t)(rowBase + lr1) * CDIM + ko + lp0 * 8);
        CP16(smem_u32(&Ws[pc][lr0][lp0 * 8]), W + (size_t)(colBase + lr0) * CDIM + ko + lp0 * 8);
        CP16(smem_u32(&Ws[pc][lr1][lp0 * 8]), W + (size_t)(colBase + lr1) * CDIM + ko + lp0 * 8);
        CP_COMMIT();
    }

#pragma unroll
    for (int kt = 0; kt < 8; ++kt) {
        const int cb = kt % 3;
        if (kt < 7) { CP_WAIT(1); } else { CP_WAIT(0); }
        __syncthreads();
        if (kt < 6) {
            const int nb = (kt + 2) % 3;
            int ko = (kt + 2) * 32;
            CP16(smem_u32(&Xs[nb][lr0][lp0 * 8]), X + (size_t)(rowBase + lr0) * CDIM + ko + lp0 * 8);
            CP16(smem_u32(&Xs[nb][lr1][lp0 * 8]), X + (size_t)(rowBase + lr1) * CDIM + ko + lp0 * 8);
            CP16(smem_u32(&Ws[nb][lr0][lp0 * 8]), W + (size_t)(colBase + lr0) * CDIM + ko + lp0 * 8);
            CP16(smem_u32(&Ws[nb][lr1][lp0 * 8]), W + (size_t)(colBase + lr1) * CDIM + ko + lp0 * 8);
            CP_COMMIT();
        }

        uint32_t a[2][2][4];
#pragma unroll
        for (int mt = 0; mt < 2; ++mt)
#pragma unroll
            for (int ks = 0; ks < 2; ++ks) {
                uint32_t addr = smem_u32(
                    &Xs[cb][wm * 32 + mt * 16 + (lane & 7) + ((lane & 8) ? 8 : 0)]
                       [ks * 16 + ((lane & 16) ? 8 : 0)]);
                LDSM_X4(a[mt][ks][0], a[mt][ks][1], a[mt][ks][2], a[mt][ks][3], addr);
            }
#pragma unroll
        for (int nt = 0; nt < 8; ++nt) {
            uint32_t b[4];
            uint32_t addr = smem_u32(&Ws[cb][wn * 64 + nt * 8 + (lane & 7)][(lane >> 3) * 8]);
            LDSM_X4(b[0], b[1], b[2], b[3], addr);
#pragma unroll
            for (int mt = 0; mt < 2; ++mt) {
                MMA_F16F32(c[mt][nt][0], c[mt][nt][1], c[mt][nt][2], c[mt][nt][3],
                           a[mt][0][0], a[mt][0][1], a[mt][0][2], a[mt][0][3], b[0], b[1]);
                MMA_F16F32(c[mt][nt][0], c[mt][nt][1], c[mt][nt][2], c[mt][nt][3],
                           a[mt][1][0], a[mt][1][1], a[mt][1][2], a[mt][1][3], b[2], b[3]);
            }
        }
    }

    float2 bj[8];
#pragma unroll
    for (int nt = 0; nt < 8; ++nt)
        bj[nt] = *(const float2*)(bias + colBase + wn * 64 + nt * 8 + tid4 * 2);

#pragma unroll
    for (int mt = 0; mt < 2; ++mt)
#pragma unroll
        for (int rh = 0; rh < 2; ++rh) {
            int grow = rowBase + wm * 32 + mt * 16 + groupID + rh * 8;
#pragma unroll
            for (int nt = 0; nt < 8; ++nt) {
                int j = colBase + wn * 64 + nt * 8 + tid4 * 2;
                size_t addr = (size_t)grow * CDIM + j;
                float2 sc = *(const float2*)(shortcut + addr);
                float2 ov;
                ov.x = c[mt][nt][rh * 2 + 0] + bj[nt].x + sc.x;
                ov.y = c[mt][nt][rh * 2 + 1] + bj[nt].y + sc.y;
                *(float2*)(Out + addr) = ov;
            }
        }
}

// ---------------------------------------------------------------------------
extern "C" void kernel_launch(void* const* d_in, const int* in_sizes, int n_in,
                              void* d_out, int out_size)
{
    const float* q  = (const float*)d_in[0];
    const float* k  = (const float*)d_in[1];
    const float* v  = (const float*)d_in[2];
    const float* Wq = (const float*)d_in[3];
    const float* bq = (const float*)d_in[4];
    const float* Wk = (const float*)d_in[5];
    const float* bk = (const float*)d_in[6];
    const float* Wv = (const float*)d_in[7];
    const float* bv = (const float*)d_in[8];
    const float* Wm = (const float*)d_in[9];
    const float* bm = (const float*)d_in[10];
    float* out = (float*)d_out;

    convert_kernel<<<(3 * XQ + 4 * WQ) / 256, 256>>>(q, k, v, Wq, Wk, Wv, Wm);
    qkv_proj_kernel<<<dim3(M_ROWS / 128, CDIM / 128, 3), 256>>>(bq, bk, bv);
    attn_mma_kernel<<<dim3(8, BTH), 128>>>();
    final_f16_kernel<<<dim3(M_ROWS / 128, CDIM / 128), 256>>>(bm, q, out);
}

// round 15
// speedup vs baseline: 1.1543x; 1.1543x over previous
#include <cuda_runtime.h>
#include <cuda_fp16.h>
#include <cstdint>
#include <math.h>

// Problem constants: b=2, t=8, L=1024, c=256, H=8, D=32
#define M_ROWS 16384
#define CDIM   256
#define NHEAD  8
#define DHEAD  32
#define LSEQ   1024
#define BTH    128

// 1/sqrt(32) folded into Q at projection epilogue
#define QSCALE 0.17677669529663687f

// Scratch (device globals) — all 16-bit tensors are fp16
// g_q16/g_k16/g_v16 are stored as SW128-swizzled 8KB tiles:
//   tile index = bth*8 + (l>>7); within tile: SW128((l&127)*64 + d*2) bytes.
__device__ __half g_x16[12582912];  // q,k,v inputs
__device__ __half g_w16[262144];    // Wq,Wk,Wv,Wm
__device__ __half g_q16[4194304];
__device__ __half g_k16[4194304];
__device__ __half g_v16[4194304];
__device__ __half g_att16[4194304]; // [bt, l, c] linear

// ---------------------------------------------------------------------------
__device__ __forceinline__ uint32_t smem_u32(const void* p) {
    uint32_t a;
    asm("{ .reg .u64 t; cvta.to.shared.u64 t, %1; cvt.u32.u64 %0, t; }" : "=r"(a) : "l"(p));
    return a;
}

#define SW128(bo) ((bo) ^ (((bo) >> 3) & 0x70))

#define LDSM_X4(r0, r1, r2, r3, addr) \
    asm volatile("ldmatrix.sync.aligned.m8n8.x4.shared.b16 {%0,%1,%2,%3}, [%4];" \
                 : "=r"(r0), "=r"(r1), "=r"(r2), "=r"(r3) : "r"(addr))
#define LDSM_X4T(r0, r1, r2, r3, addr) \
    asm volatile("ldmatrix.sync.aligned.m8n8.x4.trans.shared.b16 {%0,%1,%2,%3}, [%4];" \
                 : "=r"(r0), "=r"(r1), "=r"(r2), "=r"(r3) : "r"(addr))

// f16 operands, f32 accumulator (GEMMs, PV, row sums)
#define MMA_F16F32(c0, c1, c2, c3, a0, a1, a2, a3, b0, b1) \
    asm volatile("mma.sync.aligned.m16n8k16.row.col.f32.f16.f16.f32 " \
                 "{%0,%1,%2,%3}, {%4,%5,%6,%7}, {%8,%9}, {%0,%1,%2,%3};" \
                 : "+f"(c0), "+f"(c1), "+f"(c2), "+f"(c3) \
                 : "r"(a0), "r"(a1), "r"(a2), "r"(a3), "r"(b0), "r"(b1))

// f16 operands, f16 accumulator (QK^T): D/C are 2 packed f16x2 regs
#define MMA_F16ACC(d0, d1, a0, a1, a2, a3, b0, b1) \
    asm volatile("mma.sync.aligned.m16n8k16.row.col.f16.f16.f16.f16 " \
                 "{%0,%1}, {%2,%3,%4,%5}, {%6,%7}, {%0,%1};" \
                 : "+r"(d0), "+r"(d1) \
                 : "r"(a0), "r"(a1), "r"(a2), "r"(a3), "r"(b0), "r"(b1))

#define CVT_F16X2(r, hi, lo) \
    asm("cvt.rn.f16x2.f32 %0, %1, %2;" : "=r"(r) : "f"(hi), "f"(lo))

#define HFMA2_F16(d, a, b, cc) \
    asm("fma.rn.f16x2 %0, %1, %2, %3;" : "=r"(d) : "r"(a), "r"(b), "r"(cc))

#define CP16(dst, src) \
    asm volatile("cp.async.cg.shared.global [%0], [%1], 16;" :: "r"(dst), "l"(src))
#define CP_COMMIT() asm volatile("cp.async.commit_group;")
#define CP_WAIT(n)  asm volatile("cp.async.wait_group %0;" :: "n"(n))

// --- bulk async copy (non-tensor, sm_90 base) + mbarrier ---
#define BULK_G2S(dst, src, bytes, mbar) \
    asm volatile("cp.async.bulk.shared::cluster.global.mbarrier::complete_tx::bytes " \
                 "[%0], [%1], %2, [%3];" \
                 :: "r"(dst), "l"(src), "r"(bytes), "r"(mbar) : "memory")
#define MBAR_INIT(mbar, cnt) \
    asm volatile("mbarrier.init.shared.b64 [%0], %1;" :: "r"(mbar), "r"(cnt) : "memory")
#define MBAR_EXPECT_TX(mbar, bytes) \
    asm volatile("mbarrier.arrive.expect_tx.shared.b64 _, [%0], %1;" \
                 :: "r"(mbar), "r"(bytes) : "memory")
#define MBAR_WAIT(mbar, parity) do { \
    uint32_t _m = (mbar), _p = (parity), _d; \
    asm volatile("{ .reg .pred p; mbarrier.try_wait.parity.acquire.cta.shared::cta.b64 p, [%1], %2; selp.b32 %0, 1, 0, p; }" \
        : "=r"(_d) : "r"(_m), "r"(_p) : "memory"); \
    if (!_d) { \
        asm volatile("{ .reg .pred P1; WL%=: mbarrier.try_wait.parity.acquire.cta.shared::cta.b64 P1, [%0], %1, 0x989680; @P1 bra.uni WD%=; bra.uni WL%=; WD%=: }" \
            :: "r"(_m), "r"(_p) : "memory"); \
    } } while (0)
#define FENCE_PROXY_ASYNC() asm volatile("fence.proxy.async.shared::cta;" ::: "memory")

// f16x2 constants
#define ONES_F16X2  0x3C003C00u   // (1.0, 1.0)
#define HALF_F16X2  0x38003800u   // (0.5, 0.5)

// exp(x) for |x| <= 0.18: degree-2 Taylor in packed f16x2
__device__ __forceinline__ uint32_t exp_f16x2(uint32_t x) {
    uint32_t t;
    HFMA2_F16(t, x, HALF_F16X2, ONES_F16X2);
    HFMA2_F16(t, x, t, ONES_F16X2);
    return t;
}

// ---------------------------------------------------------------------------
// Kernel 0: fp32 -> fp16 conversion of q,k,v and the 4 weight matrices.
// ---------------------------------------------------------------------------
#define XQ 1048576
#define WQ 16384
__global__ __launch_bounds__(256) void convert_kernel(
    const float* __restrict__ q, const float* __restrict__ k, const float* __restrict__ v,
    const float* __restrict__ Wq, const float* __restrict__ Wk,
    const float* __restrict__ Wv, const float* __restrict__ Wm)
{
    int idx = blockIdx.x * 256 + threadIdx.x;
    const float* src;
    uint2* dst;
    int local;
    if (idx < 3 * XQ) {
        int sel = idx / XQ;
        local = idx - sel * XQ;
        src = (sel == 0) ? q : (sel == 1) ? k : v;
        dst = (uint2*)g_x16 + idx;
    } else {
        int wi = idx - 3 * XQ;
        int sel = wi / WQ;
        local = wi - sel * WQ;
        src = (sel == 0) ? Wq : (sel == 1) ? Wk : (sel == 2) ? Wv : Wm;
        dst = (uint2*)g_w16 + wi;
    }
    float4 vv = ((const float4*)src)[local];
    uint32_t lo, hi;
    CVT_F16X2(lo, vv.y, vv.x);
    CVT_F16X2(hi, vv.w, vv.z);
    *dst = make_uint2(lo, hi);
}

// ---------------------------------------------------------------------------
// Kernel 1: merged q/k/v fp16 GEMM projection.
// 3-stage cp.async pipeline; epilogue writes SWIZZLED TILE layout for attn.
// ---------------------------------------------------------------------------
__global__ __launch_bounds__(256, 2) void qkv_proj_kernel(
    const float* __restrict__ bq, const float* __restrict__ bk,
    const float* __restrict__ bv)
{
    __shared__ __half Xs[3][128][40];
    __shared__ __half Ws[3][128][40];

    const int sel = blockIdx.z;
    const __half* X = g_x16 + (size_t)sel * 4194304;
    const __half* W = g_w16 + sel * 65536;
    const float* bias = (sel == 0) ? bq : (sel == 1) ? bk : bv;
    const float extra = (sel == 0) ? QSCALE : 1.0f;
    char* Out = (char*)((sel == 0) ? g_q16 : (sel == 1) ? g_k16 : g_v16);

    const int tid = threadIdx.x;
    const int w = tid >> 5, lane = tid & 31;
    const int wm = w >> 1, wn = w & 1;
    const int groupID = lane >> 2, tid4 = lane & 3;
    const int rowBase = blockIdx.x * 128;
    const int colBase = blockIdx.y * 128;

    const int lr0 = tid >> 2, lp0 = tid & 3;
    const int lr1 = lr0 + 64;

    float c[2][8][4];
#pragma unroll
    for (int mt = 0; mt < 2; ++mt)
#pragma unroll
        for (int nt = 0; nt < 8; ++nt)
#pragma unroll
            for (int i = 0; i < 4; ++i) c[mt][nt][i] = 0.f;

#pragma unroll
    for (int pc = 0; pc < 2; ++pc) {
        int ko = pc * 32;
        CP16(smem_u32(&Xs[pc][lr0][lp0 * 8]), X + (size_t)(rowBase + lr0) * CDIM + ko + lp0 * 8);
        CP16(smem_u32(&Xs[pc][lr1][lp0 * 8]), X + (size_t)(rowBase + lr1) * CDIM + ko + lp0 * 8);
        CP16(smem_u32(&Ws[pc][lr0][lp0 * 8]), W + (size_t)(colBase + lr0) * CDIM + ko + lp0 * 8);
        CP16(smem_u32(&Ws[pc][lr1][lp0 * 8]), W + (size_t)(colBase + lr1) * CDIM + ko + lp0 * 8);
        CP_COMMIT();
    }

#pragma unroll
    for (int kt = 0; kt < 8; ++kt) {
        const int cb = kt % 3;
        if (kt < 7) { CP_WAIT(1); } else { CP_WAIT(0); }
        __syncthreads();
        if (kt < 6) {
            const int nb = (kt + 2) % 3;
            int ko = (kt + 2) * 32;
            CP16(smem_u32(&Xs[nb][lr0][lp0 * 8]), X + (size_t)(rowBase + lr0) * CDIM + ko + lp0 * 8);
            CP16(smem_u32(&Xs[nb][lr1][lp0 * 8]), X + (size_t)(rowBase + lr1) * CDIM + ko + lp0 * 8);
            CP16(smem_u32(&Ws[nb][lr0][lp0 * 8]), W + (size_t)(colBase + lr0) * CDIM + ko + lp0 * 8);
            CP16(smem_u32(&Ws[nb][lr1][lp0 * 8]), W + (size_t)(colBase + lr1) * CDIM + ko + lp0 * 8);
            CP_COMMIT();
        }

        uint32_t a[2][2][4];
#pragma unroll
        for (int mt = 0; mt < 2; ++mt)
#pragma unroll
            for (int ks = 0; ks < 2; ++ks) {
                uint32_t addr = smem_u32(
                    &Xs[cb][wm * 32 + mt * 16 + (lane & 7) + ((lane & 8) ? 8 : 0)]
                       [ks * 16 + ((lane & 16) ? 8 : 0)]);
                LDSM_X4(a[mt][ks][0], a[mt][ks][1], a[mt][ks][2], a[mt][ks][3], addr);
            }
#pragma unroll
        for (int nt = 0; nt < 8; ++nt) {
            uint32_t b[4];
            uint32_t addr = smem_u32(&Ws[cb][wn * 64 + nt * 8 + (lane & 7)][(lane >> 3) * 8]);
            LDSM_X4(b[0], b[1], b[2], b[3], addr);
#pragma unroll
            for (int mt = 0; mt < 2; ++mt) {
                MMA_F16F32(c[mt][nt][0], c[mt][nt][1], c[mt][nt][2], c[mt][nt][3],
                           a[mt][0][0], a[mt][0][1], a[mt][0][2], a[mt][0][3], b[0], b[1]);
                MMA_F16F32(c[mt][nt][0], c[mt][nt][1], c[mt][nt][2], c[mt][nt][3],
                           a[mt][1][0], a[mt][1][1], a[mt][1][2], a[mt][1][3], b[2], b[3]);
            }
        }
    }

    float2 bj[8];
#pragma unroll
    for (int nt = 0; nt < 8; ++nt)
        bj[nt] = *(const float2*)(bias + colBase + wn * 64 + nt * 8 + tid4 * 2);
#pragma unroll
    for (int mt = 0; mt < 2; ++mt)
#pragma unroll
        for (int nt = 0; nt < 8; ++nt) {
            c[mt][nt][0] += bj[nt].x; c[mt][nt][1] += bj[nt].y;
            c[mt][nt][2] += bj[nt].x; c[mt][nt][3] += bj[nt].y;
        }

#pragma unroll
    for (int mt = 0; mt < 2; ++mt) {
        float ss[2][2];
        ss[0][0] = ss[0][1] = ss[1][0] = ss[1][1] = 0.f;
#pragma unroll
        for (int nt = 0; nt < 8; ++nt) {
            int hd = nt >> 2;
            ss[0][hd] += c[mt][nt][0] * c[mt][nt][0] + c[mt][nt][1] * c[mt][nt][1];
            ss[1][hd] += c[mt][nt][2] * c[mt][nt][2] + c[mt][nt][3] * c[mt][nt][3];
        }
        float scl[2][2];
#pragma unroll
        for (int rh = 0; rh < 2; ++rh)
#pragma unroll
            for (int hd = 0; hd < 2; ++hd) {
                float s = ss[rh][hd];
                s += __shfl_xor_sync(0xffffffffu, s, 1);
                s += __shfl_xor_sync(0xffffffffu, s, 2);
                scl[rh][hd] = extra / fmaxf(sqrtf(s), 1e-12f);
            }
#pragma unroll
        for (int rh = 0; rh < 2; ++rh) {
            int grow = rowBase + wm * 32 + mt * 16 + groupID + rh * 8;
            int bt = grow >> 10, l = grow & 1023;
#pragma unroll
            for (int nt = 0; nt < 8; ++nt) {
                int j = colBase + wn * 64 + nt * 8 + tid4 * 2;
                int h = j >> 5, dd = j & 31;
                float sc = scl[rh][nt >> 2];
                uint32_t pk;
                CVT_F16X2(pk, c[mt][nt][rh * 2 + 1] * sc, c[mt][nt][rh * 2 + 0] * sc);
                // swizzled tile layout: tile = (bt*8+h)*8 + (l>>7)
                size_t tbase = ((size_t)((bt * NHEAD + h) * 8 + (l >> 7))) * 8192;
                uint32_t bo = (uint32_t)((l & 127) * 64 + dd * 2);
                *(uint32_t*)(Out + tbase + SW128(bo)) = pk;
            }
        }
    }
}

// ---------------------------------------------------------------------------
// Kernel 2: fp16 flash attention. K/V tiles (8KB each, gmem-contiguous,
// pre-swizzled) loaded with cp.async.bulk + mbarrier (2 ops/tile instead of
// 512 LDGSTS). Double-buffered; 32KB smem -> 3 CTAs/SM. QK^T f16-acc,
// exp in-place, row sums on tensor pipe; no online max.
// ---------------------------------------------------------------------------
__global__ __launch_bounds__(128, 3) void attn_mma_kernel()
{
    __shared__ __align__(128) __half sK[2][4096];
    __shared__ __align__(128) __half sV[2][4096];
    __shared__ uint64_t s_mbar[2];

    const int tid = threadIdx.x;
    const int w = tid >> 5, lane = tid & 31;
    const int groupID = lane >> 2, tid4 = lane & 3;
    const int bth = blockIdx.y, qt = blockIdx.x;

    const char* Qg = (const char*)g_q16 + ((size_t)bth * 8 + qt) * 8192;
    const char* Kg = (const char*)g_k16 + (size_t)bth * 65536;  // 8 tiles of 8KB
    const char* Vg = (const char*)g_v16 + (size_t)bth * 65536;

    const uint32_t mb0 = smem_u32(&s_mbar[0]);
    const uint32_t mb1 = smem_u32(&s_mbar[1]);
    if (tid == 0) { MBAR_INIT(mb0, 1); MBAR_INIT(mb1, 1); }

    // Stage Q: raw byte copy of the pre-swizzled 8KB tile into sK[0]
#pragma unroll
    for (int i = 0; i < 4; ++i) {
        int f = tid + i * 128;
        *(float4*)((char*)sK[0] + f * 16) = *(const float4*)(Qg + f * 16);
    }
    __syncthreads();

    // Q fragments (swizzled addressing)
    uint32_t qa[2][2][4];
#pragma unroll
    for (int mt = 0; mt < 2; ++mt)
#pragma unroll
        for (int kc = 0; kc < 2; ++kc) {
            int row = w * 32 + mt * 16 + (lane & 7) + ((lane & 8) ? 8 : 0);
            uint32_t bo = (uint32_t)(row * 64 + kc * 32 + ((lane & 16) ? 16 : 0));
            uint32_t addr = smem_u32((char*)sK[0] + SW128(bo));
            LDSM_X4(qa[mt][kc][0], qa[mt][kc][1], qa[mt][kc][2], qa[mt][kc][3], addr);
        }
    __syncthreads();

    // prologue: tile 0 -> buf 0 (order generic STS before async-proxy writes)
    if (tid == 0) {
        FENCE_PROXY_ASYNC();
        MBAR_EXPECT_TX(mb0, 16384u);
        BULK_G2S(smem_u32(sK[0]), Kg, 8192u, mb0);
        BULK_G2S(smem_u32(sV[0]), Vg, 8192u, mb0);
    }

    float o[2][4][4];
    float su[2][4];
#pragma unroll
    for (int mt = 0; mt < 2; ++mt) {
#pragma unroll
        for (int dn = 0; dn < 4; ++dn)
#pragma unroll
            for (int i = 0; i < 4; ++i) o[mt][dn][i] = 0.f;
#pragma unroll
        for (int i = 0; i < 4; ++i) su[mt][i] = 0.f;
    }

    for (int kt = 0; kt < 8; ++kt) {
        const int cb = kt & 1;
        MBAR_WAIT(cb ? mb1 : mb0, (kt >> 1) & 1);
        __syncthreads();   // all warps done with buffer (kt+1)&1 from iter kt-1
        if (kt < 7 && tid == 0) {
            const int nb = (kt + 1) & 1;
            const uint32_t mbn = nb ? mb1 : mb0;
            MBAR_EXPECT_TX(mbn, 16384u);
            BULK_G2S(smem_u32(sK[nb]), Kg + (size_t)(kt + 1) * 8192, 8192u, mbn);
            BULK_G2S(smem_u32(sV[nb]), Vg + (size_t)(kt + 1) * 8192, 8192u, mbn);
        }

        const char* kb_base = (const char*)sK[cb];
        const char* vb_base = (const char*)sV[cb];
#pragma unroll
        for (int half = 0; half < 2; ++half) {
#pragma unroll
            for (int kc = 0; kc < 4; ++kc) {
                uint32_t pa[2][4];
#pragma unroll
                for (int sub = 0; sub < 2; ++sub) {
                    int nbk = half * 64 + (kc * 2 + sub) * 8;
                    uint32_t kb[4];
                    uint32_t bo = (uint32_t)((nbk + (lane & 7)) * 64 + (lane >> 3) * 16);
                    uint32_t addr = smem_u32(kb_base + SW128(bo));
                    LDSM_X4(kb[0], kb[1], kb[2], kb[3], addr);
#pragma unroll
                    for (int mt = 0; mt < 2; ++mt) {
                        uint32_t d0 = 0u, d1 = 0u;
                        MMA_F16ACC(d0, d1,
                                   qa[mt][0][0], qa[mt][0][1], qa[mt][0][2], qa[mt][0][3],
                                   kb[0], kb[1]);
                        MMA_F16ACC(d0, d1,
                                   qa[mt][1][0], qa[mt][1][1], qa[mt][1][2], qa[mt][1][3],
                                   kb[2], kb[3]);
                        pa[mt][sub * 2 + 0] = exp_f16x2(d0);
                        pa[mt][sub * 2 + 1] = exp_f16x2(d1);
                    }
                }
#pragma unroll
                for (int dp = 0; dp < 2; ++dp) {
                    uint32_t vb[4];
                    int vrow = half * 64 + kc * 16 + (lane & 15);
                    uint32_t bo = (uint32_t)(vrow * 64 + dp * 32 + ((lane & 16) ? 16 : 0));
                    uint32_t addr = smem_u32(vb_base + SW128(bo));
                    LDSM_X4T(vb[0], vb[1], vb[2], vb[3], addr);
#pragma unroll
                    for (int mt = 0; mt < 2; ++mt) {
                        MMA_F16F32(o[mt][2 * dp][0], o[mt][2 * dp][1],
                                   o[mt][2 * dp][2], o[mt][2 * dp][3],
                                   pa[mt][0], pa[mt][1], pa[mt][2], pa[mt][3],
                                   vb[0], vb[1]);
                        MMA_F16F32(o[mt][2 * dp + 1][0], o[mt][2 * dp + 1][1],
                                   o[mt][2 * dp + 1][2], o[mt][2 * dp + 1][3],
                                   pa[mt][0], pa[mt][1], pa[mt][2], pa[mt][3],
                                   vb[2], vb[3]);
                    }
                }
#pragma unroll
                for (int mt = 0; mt < 2; ++mt)
                    MMA_F16F32(su[mt][0], su[mt][1], su[mt][2], su[mt][3],
                               pa[mt][0], pa[mt][1], pa[mt][2], pa[mt][3],
                               ONES_F16X2, ONES_F16X2);
            }
        }
    }

    const int bt = bth >> 3, h = bth & 7;
#pragma unroll
    for (int mt = 0; mt < 2; ++mt) {
        const float inv0 = 1.f / su[mt][0];
        const float inv1 = 1.f / su[mt][2];
        const int l0 = qt * 128 + w * 32 + mt * 16 + groupID;
#pragma unroll
        for (int dn = 0; dn < 4; ++dn) {
            int col = h * DHEAD + dn * 8 + tid4 * 2;
            uint32_t pk0, pk1;
            CVT_F16X2(pk0, o[mt][dn][1] * inv0, o[mt][dn][0] * inv0);
            CVT_F16X2(pk1, o[mt][dn][3] * inv1, o[mt][dn][2] * inv1);
            *(uint32_t*)(g_att16 + ((size_t)bt * LSEQ + l0) * CDIM + col) = pk0;
            *(uint32_t*)(g_att16 + ((size_t)bt * LSEQ + l0 + 8) * CDIM + col) = pk1;
        }
    }
}

// ---------------------------------------------------------------------------
// Kernel 3: Out = g_att16 @ Wm^T + bm + shortcut (fp32 out).
// 128x128 tiles, 3-stage cp.async pipeline, ONE barrier per chunk.
// ---------------------------------------------------------------------------
__global__ __launch_bounds__(256, 2) void final_f16_kernel(
    const float* __restrict__ bias, const float* __restrict__ shortcut,
    float* __restrict__ Out)
{
    __shared__ __half Xs[3][128][40];
    __shared__ __half Ws[3][128][40];

    const __half* X = g_att16;
    const __half* W = g_w16 + 3 * 65536;

    const int tid = threadIdx.x;
    const int w = tid >> 5, lane = tid & 31;
    const int wm = w >> 1, wn = w & 1;
    const int groupID = lane >> 2, tid4 = lane & 3;
    const int rowBase = blockIdx.x * 128;
    const int colBase = blockIdx.y * 128;

    const int lr0 = tid >> 2, lp0 = tid & 3;
    const int lr1 = lr0 + 64;

    float c[2][8][4];
#pragma unroll
    for (int mt = 0; mt < 2; ++mt)
#pragma unroll
        for (int nt = 0; nt < 8; ++nt)
#pragma unroll
            for (int i = 0; i < 4; ++i) c[mt][nt][i] = 0.f;

#pragma unroll
    for (int pc = 0; pc < 2; ++pc) {
        int ko = pc * 32;
        CP16(smem_u32(&Xs[pc][lr0][lp0 * 8]), X + (size_t)(rowBase + lr0) * CDIM + ko + lp0 * 8);
        CP16(smem_u32(&Xs[pc][lr1][lp0 * 8]), X + (size_t)(rowBase + lr1) * CDIM + ko + lp0 * 8);
        CP16(smem_u32(&Ws[pc][lr0][lp0 * 8]), W + (size_t)(colBase + lr0) * CDIM + ko + lp0 * 8);
        CP16(smem_u32(&Ws[pc][lr1][lp0 * 8]), W + (size_t)(colBase + lr1) * CDIM + ko + lp0 * 8);
        CP_COMMIT();
    }

#pragma unroll
    for (int kt = 0; kt < 8; ++kt) {
        const int cb = kt % 3;
        if (kt < 7) { CP_WAIT(1); } else { CP_WAIT(0); }
        __syncthreads();
        if (kt < 6) {
            const int nb = (kt + 2) % 3;
            int ko = (kt + 2) * 32;
            CP16(smem_u32(&Xs[nb][lr0][lp0 * 8]), X + (size_t)(rowBase + lr0) * CDIM + ko + lp0 * 8);
            CP16(smem_u32(&Xs[nb][lr1][lp0 * 8]), X + (size_t)(rowBase + lr1) * CDIM + ko + lp0 * 8);
            CP16(smem_u32(&Ws[nb][lr0][lp0 * 8]), W + (size_t)(colBase + lr0) * CDIM + ko + lp0 * 8);
            CP16(smem_u32(&Ws[nb][lr1][lp0 * 8]), W + (size_t)(colBase + lr1) * CDIM + ko + lp0 * 8);
            CP_COMMIT();
        }

        uint32_t a[2][2][4];
#pragma unroll
        for (int mt = 0; mt < 2; ++mt)
#pragma unroll
            for (int ks = 0; ks < 2; ++ks) {
                uint32_t addr = smem_u32(
                    &Xs[cb][wm * 32 + mt * 16 + (lane & 7) + ((lane & 8) ? 8 : 0)]
                       [ks * 16 + ((lane & 16) ? 8 : 0)]);
                LDSM_X4(a[mt][ks][0], a[mt][ks][1], a[mt][ks][2], a[mt][ks][3], addr);
            }
#pragma unroll
        for (int nt = 0; nt < 8; ++nt) {
            uint32_t b[4];
            uint32_t addr = smem_u32(&Ws[cb][wn * 64 + nt * 8 + (lane & 7)][(lane >> 3) * 8]);
            LDSM_X4(b[0], b[1], b[2], b[3], addr);
#pragma unroll
            for (int mt = 0; mt < 2; ++mt) {
                MMA_F16F32(c[mt][nt][0], c[mt][nt][1], c[mt][nt][2], c[mt][nt][3],
                           a[mt][0][0], a[mt][0][1], a[mt][0][2], a[mt][0][3], b[0], b[1]);
                MMA_F16F32(c[mt][nt][0], c[mt][nt][1], c[mt][nt][2], c[mt][nt][3],
                           a[mt][1][0], a[mt][1][1], a[mt][1][2], a[mt][1][3], b[2], b[3]);
            }
        }
    }

    float2 bj[8];
#pragma unroll
    for (int nt = 0; nt < 8; ++nt)
        bj[nt] = *(const float2*)(bias + colBase + wn * 64 + nt * 8 + tid4 * 2);

#pragma unroll
    for (int mt = 0; mt < 2; ++mt)
#pragma unroll
        for (int rh = 0; rh < 2; ++rh) {
            int grow = rowBase + wm * 32 + mt * 16 + groupID + rh * 8;
#pragma unroll
            for (int nt = 0; nt < 8; ++nt) {
                int j = colBase + wn * 64 + nt * 8 + tid4 * 2;
                size_t addr = (size_t)grow * CDIM + j;
                float2 sc = *(const float2*)(shortcut + addr);
                float2 ov;
                ov.x = c[mt][nt][rh * 2 + 0] + bj[nt].x + sc.x;
                ov.y = c[mt][nt][rh * 2 + 1] + bj[nt].y + sc.y;
                *(float2*)(Out + addr) = ov;
            }
        }
}

// ---------------------------------------------------------------------------
extern "C" void kernel_launch(void* const* d_in, const int* in_sizes, int n_in,
                              void* d_out, int out_size)
{
    const float* q  = (const float*)d_in[0];
    const float* k  = (const float*)d_in[1];
    const float* v  = (const float*)d_in[2];
    const float* Wq = (const float*)d_in[3];
    const float* bq = (const float*)d_in[4];
    const float* Wk = (const float*)d_in[5];
    const float* bk = (const float*)d_in[6];
    const float* Wv = (const float*)d_in[7];
    const float* bv = (const float*)d_in[8];
    const float* Wm = (const float*)d_in[9];
    const float* bm = (const float*)d_in[10];
    float* out = (float*)d_out;

    convert_kernel<<<(3 * XQ + 4 * WQ) / 256, 256>>>(q, k, v, Wq, Wk, Wv, Wm);
    qkv_proj_kernel<<<dim3(M_ROWS / 128, CDIM / 128, 3), 256>>>(bq, bk, bv);
    attn_mma_kernel<<<dim3(8, BTH), 128>>>();
    final_f16_kernel<<<dim3(M_ROWS / 128, CDIM / 128), 256>>>(bm, q, out);
}

// round 16
// speedup vs baseline: 1.3250x; 1.1479x over previous
#include <cuda_runtime.h>
#include <cuda_fp16.h>
#include <cstdint>
#include <math.h>

// Problem constants: b=2, t=8, L=1024, c=256, H=8, D=32
#define M_ROWS 16384
#define CDIM   256
#define NHEAD  8
#define DHEAD  32
#define LSEQ   1024
#define BTH    128

// 1/sqrt(32) folded into Q at projection epilogue
#define QSCALE 0.17677669529663687f

// Scratch (device globals) — all fp16 tensors stored as SW128-swizzled 8KB
// tiles: tile = (row>>7)*8 + (col>>5); within: SW128((row&127)*64 + (col&31)*2).
__device__ __half g_x16[12582912];  // q,k,v inputs   (tiled)
__device__ __half g_w16[262144];    // Wq,Wk,Wv,Wm    (tiled)
__device__ __half g_q16[4194304];   // tiled [bth*8+qt]
__device__ __half g_k16[4194304];
__device__ __half g_v16[4194304];
__device__ __half g_att16[4194304]; // tiled [(bt*8+qt)*8+h]

// ---------------------------------------------------------------------------
__device__ __forceinline__ uint32_t smem_u32(const void* p) {
    uint32_t a;
    asm("{ .reg .u64 t; cvta.to.shared.u64 t, %1; cvt.u32.u64 %0, t; }" : "=r"(a) : "l"(p));
    return a;
}

#define SW128(bo) ((bo) ^ (((bo) >> 3) & 0x70))

#define LDSM_X4(r0, r1, r2, r3, addr) \
    asm volatile("ldmatrix.sync.aligned.m8n8.x4.shared.b16 {%0,%1,%2,%3}, [%4];" \
                 : "=r"(r0), "=r"(r1), "=r"(r2), "=r"(r3) : "r"(addr))
#define LDSM_X4T(r0, r1, r2, r3, addr) \
    asm volatile("ldmatrix.sync.aligned.m8n8.x4.trans.shared.b16 {%0,%1,%2,%3}, [%4];" \
                 : "=r"(r0), "=r"(r1), "=r"(r2), "=r"(r3) : "r"(addr))

#define MMA_F16F32(c0, c1, c2, c3, a0, a1, a2, a3, b0, b1) \
    asm volatile("mma.sync.aligned.m16n8k16.row.col.f32.f16.f16.f32 " \
                 "{%0,%1,%2,%3}, {%4,%5,%6,%7}, {%8,%9}, {%0,%1,%2,%3};" \
                 : "+f"(c0), "+f"(c1), "+f"(c2), "+f"(c3) \
                 : "r"(a0), "r"(a1), "r"(a2), "r"(a3), "r"(b0), "r"(b1))

#define MMA_F16ACC(d0, d1, a0, a1, a2, a3, b0, b1) \
    asm volatile("mma.sync.aligned.m16n8k16.row.col.f16.f16.f16.f16 " \
                 "{%0,%1}, {%2,%3,%4,%5}, {%6,%7}, {%0,%1};" \
                 : "+r"(d0), "+r"(d1) \
                 : "r"(a0), "r"(a1), "r"(a2), "r"(a3), "r"(b0), "r"(b1))

#define CVT_F16X2(r, hi, lo) \
    asm("cvt.rn.f16x2.f32 %0, %1, %2;" : "=r"(r) : "f"(hi), "f"(lo))

#define HFMA2_F16(d, a, b, cc) \
    asm("fma.rn.f16x2 %0, %1, %2, %3;" : "=r"(d) : "r"(a), "r"(b), "r"(cc))

// --- bulk async copy + mbarrier ---
#define BULK_G2S(dst, src, bytes, mbar) \
    asm volatile("cp.async.bulk.shared::cluster.global.mbarrier::complete_tx::bytes " \
                 "[%0], [%1], %2, [%3];" \
                 :: "r"(dst), "l"(src), "r"(bytes), "r"(mbar) : "memory")
#define MBAR_INIT(mbar, cnt) \
    asm volatile("mbarrier.init.shared.b64 [%0], %1;" :: "r"(mbar), "r"(cnt) : "memory")
#define MBAR_EXPECT_TX(mbar, bytes) \
    asm volatile("mbarrier.arrive.expect_tx.shared.b64 _, [%0], %1;" \
                 :: "r"(mbar), "r"(bytes) : "memory")
#define MBAR_WAIT(mbar, parity) do { \
    uint32_t _m = (mbar), _p = (parity), _d; \
    asm volatile("{ .reg .pred p; mbarrier.try_wait.parity.acquire.cta.shared::cta.b64 p, [%1], %2; selp.b32 %0, 1, 0, p; }" \
        : "=r"(_d) : "r"(_m), "r"(_p) : "memory"); \
    if (!_d) { \
        asm volatile("{ .reg .pred P1; WL%=: mbarrier.try_wait.parity.acquire.cta.shared::cta.b64 P1, [%0], %1, 0x989680; @P1 bra.uni WD%=; bra.uni WL%=; WD%=: }" \
            :: "r"(_m), "r"(_p) : "memory"); \
    } } while (0)
#define FENCE_PROXY_ASYNC() asm volatile("fence.proxy.async.shared::cta;" ::: "memory")

// f16x2 constants
#define ONES_F16X2  0x3C003C00u
#define HALF_F16X2  0x38003800u

__device__ __forceinline__ uint32_t exp_f16x2(uint32_t x) {
    uint32_t t;
    HFMA2_F16(t, x, HALF_F16X2, ONES_F16X2);
    HFMA2_F16(t, x, t, ONES_F16X2);
    return t;
}

// ---------------------------------------------------------------------------
// Kernel 0: fp32 -> fp16 conversion; writes swizzled 8KB-tile layout.
// ---------------------------------------------------------------------------
#define XQ 1048576
#define WQ 16384
__global__ __launch_bounds__(256) void convert_kernel(
    const float* __restrict__ q, const float* __restrict__ k, const float* __restrict__ v,
    const float* __restrict__ Wq, const float* __restrict__ Wk,
    const float* __restrict__ Wv, const float* __restrict__ Wm)
{
    int idx = blockIdx.x * 256 + threadIdx.x;
    const float* src;
    char* base;
    int local;
    if (idx < 3 * XQ) {
        int sel = idx / XQ;
        local = idx - sel * XQ;
        src = (sel == 0) ? q : (sel == 1) ? k : v;
        base = (char*)g_x16 + (size_t)sel * 8388608;
    } else {
        int wi = idx - 3 * XQ;
        int sel = wi / WQ;
        local = wi - sel * WQ;
        src = (sel == 0) ? Wq : (sel == 1) ? Wk : (sel == 2) ? Wv : Wm;
        base = (char*)g_w16 + (size_t)sel * 131072;
    }
    float4 vv = ((const float4*)src)[local];
    uint32_t lo, hi;
    CVT_F16X2(lo, vv.y, vv.x);
    CVT_F16X2(hi, vv.w, vv.z);
    int r = local >> 6;          // matrix row
    int cq = (local & 63) * 4;   // first col of the 4-elem quad
    size_t tbase = ((size_t)((r >> 7) * 8 + (cq >> 5))) * 8192;
    uint32_t bo = (uint32_t)((r & 127) * 64 + (cq & 31) * 2);
    *(uint2*)(base + tbase + SW128(bo)) = make_uint2(lo, hi);
}

// ---------------------------------------------------------------------------
// Kernel 1: merged q/k/v fp16 GEMM projection. Bulk-copied swizzled tiles,
// 3-stage mbarrier ring (prefetch distance 2).
// ---------------------------------------------------------------------------
__global__ __launch_bounds__(256, 2) void qkv_proj_kernel(
    const float* __restrict__ bq, const float* __restrict__ bk,
    const float* __restrict__ bv)
{
    __shared__ __align__(128) __half Xs[3][4096];   // 8KB tiles
    __shared__ __align__(128) __half Ws[3][4096];
    __shared__ uint64_t s_mbar[3];

    const int sel = blockIdx.z;
    const char* Xg = (const char*)g_x16 + (size_t)sel * 8388608
                   + (size_t)blockIdx.x * 8 * 8192;           // rowBlock tiles
    const char* Wg = (const char*)g_w16 + (size_t)sel * 131072
                   + (size_t)blockIdx.y * 8 * 8192;           // colBlock tiles
    const float* bias = (sel == 0) ? bq : (sel == 1) ? bk : bv;
    const float extra = (sel == 0) ? QSCALE : 1.0f;
    char* Out = (char*)((sel == 0) ? g_q16 : (sel == 1) ? g_k16 : g_v16);

    const int tid = threadIdx.x;
    const int w = tid >> 5, lane = tid & 31;
    const int wm = w >> 1, wn = w & 1;
    const int groupID = lane >> 2, tid4 = lane & 3;
    const int rowBase = blockIdx.x * 128;
    const int colBase = blockIdx.y * 128;

    uint32_t mb[3];
    mb[0] = smem_u32(&s_mbar[0]); mb[1] = smem_u32(&s_mbar[1]); mb[2] = smem_u32(&s_mbar[2]);
    if (tid == 0) { MBAR_INIT(mb[0], 1); MBAR_INIT(mb[1], 1); MBAR_INIT(mb[2], 1); }
    __syncthreads();

    if (tid == 0) {
        FENCE_PROXY_ASYNC();
#pragma unroll
        for (int pc = 0; pc < 2; ++pc) {
            MBAR_EXPECT_TX(mb[pc], 16384u);
            BULK_G2S(smem_u32(Xs[pc]), Xg + (size_t)pc * 8192, 8192u, mb[pc]);
            BULK_G2S(smem_u32(Ws[pc]), Wg + (size_t)pc * 8192, 8192u, mb[pc]);
        }
    }

    float c[2][8][4];
#pragma unroll
    for (int mt = 0; mt < 2; ++mt)
#pragma unroll
        for (int nt = 0; nt < 8; ++nt)
#pragma unroll
            for (int i = 0; i < 4; ++i) c[mt][nt][i] = 0.f;

    for (int kt = 0; kt < 8; ++kt) {
        const int cb = kt % 3;
        MBAR_WAIT(mb[cb], (kt / 3) & 1);
        __syncthreads();
        if (kt < 6 && tid == 0) {
            const int nb = (kt + 2) % 3;
            MBAR_EXPECT_TX(mb[nb], 16384u);
            BULK_G2S(smem_u32(Xs[nb]), Xg + (size_t)(kt + 2) * 8192, 8192u, mb[nb]);
            BULK_G2S(smem_u32(Ws[nb]), Wg + (size_t)(kt + 2) * 8192, 8192u, mb[nb]);
        }

        const char* xb = (const char*)Xs[cb];
        const char* wb = (const char*)Ws[cb];
        uint32_t a[2][2][4];
#pragma unroll
        for (int mt = 0; mt < 2; ++mt)
#pragma unroll
            for (int ks = 0; ks < 2; ++ks) {
                int row = wm * 32 + mt * 16 + (lane & 7) + ((lane & 8) ? 8 : 0);
                uint32_t bo = (uint32_t)(row * 64 + ks * 32 + ((lane & 16) ? 16 : 0));
                uint32_t addr = smem_u32(xb + SW128(bo));
                LDSM_X4(a[mt][ks][0], a[mt][ks][1], a[mt][ks][2], a[mt][ks][3], addr);
            }
#pragma unroll
        for (int nt = 0; nt < 8; ++nt) {
            uint32_t b[4];
            int row = wn * 64 + nt * 8 + (lane & 7);
            uint32_t bo = (uint32_t)(row * 64 + (lane >> 3) * 16);
            uint32_t addr = smem_u32(wb + SW128(bo));
            LDSM_X4(b[0], b[1], b[2], b[3], addr);
#pragma unroll
            for (int mt = 0; mt < 2; ++mt) {
                MMA_F16F32(c[mt][nt][0], c[mt][nt][1], c[mt][nt][2], c[mt][nt][3],
                           a[mt][0][0], a[mt][0][1], a[mt][0][2], a[mt][0][3], b[0], b[1]);
                MMA_F16F32(c[mt][nt][0], c[mt][nt][1], c[mt][nt][2], c[mt][nt][3],
                           a[mt][1][0], a[mt][1][1], a[mt][1][2], a[mt][1][3], b[2], b[3]);
            }
        }
    }

    float2 bj[8];
#pragma unroll
    for (int nt = 0; nt < 8; ++nt)
        bj[nt] = *(const float2*)(bias + colBase + wn * 64 + nt * 8 + tid4 * 2);
#pragma unroll
    for (int mt = 0; mt < 2; ++mt)
#pragma unroll
        for (int nt = 0; nt < 8; ++nt) {
            c[mt][nt][0] += bj[nt].x; c[mt][nt][1] += bj[nt].y;
            c[mt][nt][2] += bj[nt].x; c[mt][nt][3] += bj[nt].y;
        }

#pragma unroll
    for (int mt = 0; mt < 2; ++mt) {
        float ss[2][2];
        ss[0][0] = ss[0][1] = ss[1][0] = ss[1][1] = 0.f;
#pragma unroll
        for (int nt = 0; nt < 8; ++nt) {
            int hd = nt >> 2;
            ss[0][hd] += c[mt][nt][0] * c[mt][nt][0] + c[mt][nt][1] * c[mt][nt][1];
            ss[1][hd] += c[mt][nt][2] * c[mt][nt][2] + c[mt][nt][3] * c[mt][nt][3];
        }
        float scl[2][2];
#pragma unroll
        for (int rh = 0; rh < 2; ++rh)
#pragma unroll
            for (int hd = 0; hd < 2; ++hd) {
                float s = ss[rh][hd];
                s += __shfl_xor_sync(0xffffffffu, s, 1);
                s += __shfl_xor_sync(0xffffffffu, s, 2);
                scl[rh][hd] = extra / fmaxf(sqrtf(s), 1e-12f);
            }
#pragma unroll
        for (int rh = 0; rh < 2; ++rh) {
            int grow = rowBase + wm * 32 + mt * 16 + groupID + rh * 8;
            int bt = grow >> 10, l = grow & 1023;
#pragma unroll
            for (int nt = 0; nt < 8; ++nt) {
                int j = colBase + wn * 64 + nt * 8 + tid4 * 2;
                int h = j >> 5, dd = j & 31;
                float sc = scl[rh][nt >> 2];
                uint32_t pk;
                CVT_F16X2(pk, c[mt][nt][rh * 2 + 1] * sc, c[mt][nt][rh * 2 + 0] * sc);
                size_t tbase = ((size_t)((bt * NHEAD + h) * 8 + (l >> 7))) * 8192;
                uint32_t bo = (uint32_t)((l & 127) * 64 + dd * 2);
                *(uint32_t*)(Out + tbase + SW128(bo)) = pk;
            }
        }
    }
}

// ---------------------------------------------------------------------------
// Kernel 2: fp16 flash attention (unchanged from R15 except tiled g_att16
// epilogue). Bulk-copied K/V, double-buffered, 3 CTAs/SM.
// ---------------------------------------------------------------------------
__global__ __launch_bounds__(128, 3) void attn_mma_kernel()
{
    __shared__ __align__(128) __half sK[2][4096];
    __shared__ __align__(128) __half sV[2][4096];
    __shared__ uint64_t s_mbar[2];

    const int tid = threadIdx.x;
    const int w = tid >> 5, lane = tid & 31;
    const int groupID = lane >> 2, tid4 = lane & 3;
    const int bth = blockIdx.y, qt = blockIdx.x;

    const char* Qg = (const char*)g_q16 + ((size_t)bth * 8 + qt) * 8192;
    const char* Kg = (const char*)g_k16 + (size_t)bth * 65536;
    const char* Vg = (const char*)g_v16 + (size_t)bth * 65536;

    const uint32_t mb0 = smem_u32(&s_mbar[0]);
    const uint32_t mb1 = smem_u32(&s_mbar[1]);
    if (tid == 0) { MBAR_INIT(mb0, 1); MBAR_INIT(mb1, 1); }

    // Stage Q: raw copy of the pre-swizzled 8KB tile into sK[0]
#pragma unroll
    for (int i = 0; i < 4; ++i) {
        int f = tid + i * 128;
        *(float4*)((char*)sK[0] + f * 16) = *(const float4*)(Qg + f * 16);
    }
    __syncthreads();

    uint32_t qa[2][2][4];
#pragma unroll
    for (int mt = 0; mt < 2; ++mt)
#pragma unroll
        for (int kc = 0; kc < 2; ++kc) {
            int row = w * 32 + mt * 16 + (lane & 7) + ((lane & 8) ? 8 : 0);
            uint32_t bo = (uint32_t)(row * 64 + kc * 32 + ((lane & 16) ? 16 : 0));
            uint32_t addr = smem_u32((char*)sK[0] + SW128(bo));
            LDSM_X4(qa[mt][kc][0], qa[mt][kc][1], qa[mt][kc][2], qa[mt][kc][3], addr);
        }
    __syncthreads();

    if (tid == 0) {
        FENCE_PROXY_ASYNC();
        MBAR_EXPECT_TX(mb0, 16384u);
        BULK_G2S(smem_u32(sK[0]), Kg, 8192u, mb0);
        BULK_G2S(smem_u32(sV[0]), Vg, 8192u, mb0);
    }

    float o[2][4][4];
    float su[2][4];
#pragma unroll
    for (int mt = 0; mt < 2; ++mt) {
#pragma unroll
        for (int dn = 0; dn < 4; ++dn)
#pragma unroll
            for (int i = 0; i < 4; ++i) o[mt][dn][i] = 0.f;
#pragma unroll
        for (int i = 0; i < 4; ++i) su[mt][i] = 0.f;
    }

    for (int kt = 0; kt < 8; ++kt) {
        const int cb = kt & 1;
        MBAR_WAIT(cb ? mb1 : mb0, (kt >> 1) & 1);
        __syncthreads();
        if (kt < 7 && tid == 0) {
            const int nb = (kt + 1) & 1;
            const uint32_t mbn = nb ? mb1 : mb0;
            MBAR_EXPECT_TX(mbn, 16384u);
            BULK_G2S(smem_u32(sK[nb]), Kg + (size_t)(kt + 1) * 8192, 8192u, mbn);
            BULK_G2S(smem_u32(sV[nb]), Vg + (size_t)(kt + 1) * 8192, 8192u, mbn);
        }

        const char* kb_base = (const char*)sK[cb];
        const char* vb_base = (const char*)sV[cb];
#pragma unroll
        for (int half = 0; half < 2; ++half) {
#pragma unroll
            for (int kc = 0; kc < 4; ++kc) {
                uint32_t pa[2][4];
#pragma unroll
                for (int sub = 0; sub < 2; ++sub) {
                    int nbk = half * 64 + (kc * 2 + sub) * 8;
                    uint32_t kb[4];
                    uint32_t bo = (uint32_t)((nbk + (lane & 7)) * 64 + (lane >> 3) * 16);
                    uint32_t addr = smem_u32(kb_base + SW128(bo));
                    LDSM_X4(kb[0], kb[1], kb[2], kb[3], addr);
#pragma unroll
                    for (int mt = 0; mt < 2; ++mt) {
                        uint32_t d0 = 0u, d1 = 0u;
                        MMA_F16ACC(d0, d1,
                                   qa[mt][0][0], qa[mt][0][1], qa[mt][0][2], qa[mt][0][3],
                                   kb[0], kb[1]);
                        MMA_F16ACC(d0, d1,
                                   qa[mt][1][0], qa[mt][1][1], qa[mt][1][2], qa[mt][1][3],
                                   kb[2], kb[3]);
                        pa[mt][sub * 2 + 0] = exp_f16x2(d0);
                        pa[mt][sub * 2 + 1] = exp_f16x2(d1);
                    }
                }
#pragma unroll
                for (int dp = 0; dp < 2; ++dp) {
                    uint32_t vb[4];
                    int vrow = half * 64 + kc * 16 + (lane & 15);
                    uint32_t bo = (uint32_t)(vrow * 64 + dp * 32 + ((lane & 16) ? 16 : 0));
                    uint32_t addr = smem_u32(vb_base + SW128(bo));
                    LDSM_X4T(vb[0], vb[1], vb[2], vb[3], addr);
#pragma unroll
                    for (int mt = 0; mt < 2; ++mt) {
                        MMA_F16F32(o[mt][2 * dp][0], o[mt][2 * dp][1],
                                   o[mt][2 * dp][2], o[mt][2 * dp][3],
                                   pa[mt][0], pa[mt][1], pa[mt][2], pa[mt][3],
                                   vb[0], vb[1]);
                        MMA_F16F32(o[mt][2 * dp + 1][0], o[mt][2 * dp + 1][1],
                                   o[mt][2 * dp + 1][2], o[mt][2 * dp + 1][3],
                                   pa[mt][0], pa[mt][1], pa[mt][2], pa[mt][3],
                                   vb[2], vb[3]);
                    }
                }
#pragma unroll
                for (int mt = 0; mt < 2; ++mt)
                    MMA_F16F32(su[mt][0], su[mt][1], su[mt][2], su[mt][3],
                               pa[mt][0], pa[mt][1], pa[mt][2], pa[mt][3],
                               ONES_F16X2, ONES_F16X2);
            }
        }
    }

    const int bt = bth >> 3, h = bth & 7;
#pragma unroll
    for (int mt = 0; mt < 2; ++mt) {
        const float inv0 = 1.f / su[mt][0];
        const float inv1 = 1.f / su[mt][2];
        const int lr = w * 32 + mt * 16 + groupID;   // row within 128-tile
        size_t tbase = ((size_t)((bt * 8 + qt) * 8 + h)) * 8192;
#pragma unroll
        for (int dn = 0; dn < 4; ++dn) {
            int cb2 = (dn * 8 + tid4 * 2) * 2;  // byte col within 64B row
            uint32_t pk0, pk1;
            CVT_F16X2(pk0, o[mt][dn][1] * inv0, o[mt][dn][0] * inv0);
            CVT_F16X2(pk1, o[mt][dn][3] * inv1, o[mt][dn][2] * inv1);
            *(uint32_t*)((char*)g_att16 + tbase + SW128((uint32_t)(lr * 64 + cb2))) = pk0;
            *(uint32_t*)((char*)g_att16 + tbase + SW128((uint32_t)((lr + 8) * 64 + cb2))) = pk1;
        }
    }
}

// ---------------------------------------------------------------------------
// Kernel 3: Out = att @ Wm^T + bm + shortcut (fp32 out). Bulk-copied
// swizzled tiles, 3-stage mbarrier ring.
// ---------------------------------------------------------------------------
__global__ __launch_bounds__(256, 2) void final_f16_kernel(
    const float* __restrict__ bias, const float* __restrict__ shortcut,
    float* __restrict__ Out)
{
    __shared__ __align__(128) __half Xs[3][4096];
    __shared__ __align__(128) __half Ws[3][4096];
    __shared__ uint64_t s_mbar[3];

    const char* Xg = (const char*)g_att16 + (size_t)blockIdx.x * 8 * 8192;
    const char* Wg = (const char*)g_w16 + 3 * 131072 + (size_t)blockIdx.y * 8 * 8192;

    const int tid = threadIdx.x;
    const int w = tid >> 5, lane = tid & 31;
    const int wm = w >> 1, wn = w & 1;
    const int groupID = lane >> 2, tid4 = lane & 3;
    const int rowBase = blockIdx.x * 128;
    const int colBase = blockIdx.y * 128;

    uint32_t mb[3];
    mb[0] = smem_u32(&s_mbar[0]); mb[1] = smem_u32(&s_mbar[1]); mb[2] = smem_u32(&s_mbar[2]);
    if (tid == 0) { MBAR_INIT(mb[0], 1); MBAR_INIT(mb[1], 1); MBAR_INIT(mb[2], 1); }
    __syncthreads();

    if (tid == 0) {
        FENCE_PROXY_ASYNC();
#pragma unroll
        for (int pc = 0; pc < 2; ++pc) {
            MBAR_EXPECT_TX(mb[pc], 16384u);
            BULK_G2S(smem_u32(Xs[pc]), Xg + (size_t)pc * 8192, 8192u, mb[pc]);
            BULK_G2S(smem_u32(Ws[pc]), Wg + (size_t)pc * 8192, 8192u, mb[pc]);
        }
    }

    float c[2][8][4];
#pragma unroll
    for (int mt = 0; mt < 2; ++mt)
#pragma unroll
        for (int nt = 0; nt < 8; ++nt)
#pragma unroll
            for (int i = 0; i < 4; ++i) c[mt][nt][i] = 0.f;

    for (int kt = 0; kt < 8; ++kt) {
        const int cb = kt % 3;
        MBAR_WAIT(mb[cb], (kt / 3) & 1);
        __syncthreads();
        if (kt < 6 && tid == 0) {
            const int nb = (kt + 2) % 3;
            MBAR_EXPECT_TX(mb[nb], 16384u);
            BULK_G2S(smem_u32(Xs[nb]), Xg + (size_t)(kt + 2) * 8192, 8192u, mb[nb]);
            BULK_G2S(smem_u32(Ws[nb]), Wg + (size_t)(kt + 2) * 8192, 8192u, mb[nb]);
        }

        const char* xb = (const char*)Xs[cb];
        const char* wb = (const char*)Ws[cb];
        uint32_t a[2][2][4];
#pragma unroll
        for (int mt = 0; mt < 2; ++mt)
#pragma unroll
            for (int ks = 0; ks < 2; ++ks) {
                int row = wm * 32 + mt * 16 + (lane & 7) + ((lane & 8) ? 8 : 0);
                uint32_t bo = (uint32_t)(row * 64 + ks * 32 + ((lane & 16) ? 16 : 0));
                uint32_t addr = smem_u32(xb + SW128(bo));
                LDSM_X4(a[mt][ks][0], a[mt][ks][1], a[mt][ks][2], a[mt][ks][3], addr);
            }
#pragma unroll
        for (int nt = 0; nt < 8; ++nt) {
            uint32_t b[4];
            int row = wn * 64 + nt * 8 + (lane & 7);
            uint32_t bo = (uint32_t)(row * 64 + (lane >> 3) * 16);
            uint32_t addr = smem_u32(wb + SW128(bo));
            LDSM_X4(b[0], b[1], b[2], b[3], addr);
#pragma unroll
            for (int mt = 0; mt < 2; ++mt) {
                MMA_F16F32(c[mt][nt][0], c[mt][nt][1], c[mt][nt][2], c[mt][nt][3],
                           a[mt][0][0], a[mt][0][1], a[mt][0][2], a[mt][0][3], b[0], b[1]);
                MMA_F16F32(c[mt][nt][0], c[mt][nt][1], c[mt][nt][2], c[mt][nt][3],
                           a[mt][1][0], a[mt][1][1], a[mt][1][2], a[mt][1][3], b[2], b[3]);
            }
        }
    }

    float2 bj[8];
#pragma unroll
    for (int nt = 0; nt < 8; ++nt)
        bj[nt] = *(const float2*)(bias + colBase + wn * 64 + nt * 8 + tid4 * 2);

#pragma unroll
    for (int mt = 0; mt < 2; ++mt)
#pragma unroll
        for (int rh = 0; rh < 2; ++rh) {
            int grow = rowBase + wm * 32 + mt * 16 + groupID + rh * 8;
#pragma unroll
            for (int nt = 0; nt < 8; ++nt) {
                int j = colBase + wn * 64 + nt * 8 + tid4 * 2;
                size_t addr = (size_t)grow * CDIM + j;
                float2 sc = *(const float2*)(shortcut + addr);
                float2 ov;
                ov.x = c[mt][nt][rh * 2 + 0] + bj[nt].x + sc.x;
                ov.y = c[mt][nt][rh * 2 + 1] + bj[nt].y + sc.y;
                *(float2*)(Out + addr) = ov;
            }
        }
}

// ---------------------------------------------------------------------------
extern "C" void kernel_launch(void* const* d_in, const int* in_sizes, int n_in,
                              void* d_out, int out_size)
{
    const float* q  = (const float*)d_in[0];
    const float* k  = (const float*)d_in[1];
    const float* v  = (const float*)d_in[2];
    const float* Wq = (const float*)d_in[3];
    const float* bq = (const float*)d_in[4];
    const float* Wk = (const float*)d_in[5];
    const float* bk = (const float*)d_in[6];
    const float* Wv = (const float*)d_in[7];
    const float* bv = (const float*)d_in[8];
    const float* Wm = (const float*)d_in[9];
    const float* bm = (const float*)d_in[10];
    float* out = (float*)d_out;

    convert_kernel<<<(3 * XQ + 4 * WQ) / 256, 256>>>(q, k, v, Wq, Wk, Wv, Wm);
    qkv_proj_kernel<<<dim3(M_ROWS / 128, CDIM / 128, 3), 256>>>(bq, bk, bv);
    attn_mma_kernel<<<dim3(8, BTH), 128>>>();
    final_f16_kernel<<<dim3(M_ROWS / 128, CDIM / 128), 256>>>(bm, q, out);
}